// round 16
// baseline (speedup 1.0000x reference)
#include <cuda_runtime.h>

// Problem constants: B=8, CIN=COUT=128, H=W=64
#define NB   8
#define NC   128
#define NH   64
#define NW   64

// Scratch (device globals — no allocation allowed)
__device__ __align__(16) float g_xt[NB * NH * NW * NC];   // NHWC input, 16 MB
__device__ __align__(16) float g_off[NB * NH * NW * 4];   // shift_y, shift_x, scale1, scale2
__device__ __align__(16) float g_wt7[9 * 16 * 1024];      // [k][og16][1024] linear rows

__constant__ float c_BY[9] = {-1,-1,-1, 0,0,0, 1,1,1};
__constant__ float c_BX[9] = {-1, 0, 1,-1,0,1,-1,0,1};

extern __shared__ float dsm[];

// k_main smem: A0 [32][132]=4224 | A1 4224  -> 8448 floats (33792 B)
#define KMAIN_SMEM (8448 * 4)

// ---------------------------------------------------------------------------
// Kernel 1: NCHW -> NHWC transpose
// ---------------------------------------------------------------------------
__global__ void k_transpose(const float* __restrict__ x) {
    __shared__ float tile[32][33];
    int bh = blockIdx.x;
    int b = bh >> 6, h = bh & 63;
    int c0 = blockIdx.y * 32;
    int w0 = blockIdx.z * 32;
    int tx = threadIdx.x, ty = threadIdx.y;
#pragma unroll
    for (int q = 0; q < 4; q++) {
        int c = c0 + ty + 8 * q;
        tile[ty + 8 * q][tx] = x[(((b * NC + c) * NH + h) * NW) + w0 + tx];
    }
    __syncthreads();
#pragma unroll
    for (int q = 0; q < 4; q++) {
        int w = w0 + ty + 8 * q;
        g_xt[((b * NH + h) * NW + w) * NC + c0 + tx] = tile[tx][ty + 8 * q];
    }
}

// ---------------------------------------------------------------------------
// Kernel 2: weight image. g_wt7[k][og][e], e = c4*32 + pair*16 + ou*2 + j:
//   o = og*8 + ou,  c = c4*4 + pair*2 + j
// ---------------------------------------------------------------------------
__global__ void k_wt7(const float* __restrict__ w) {
    int i = blockIdx.x * 256 + threadIdx.x;
    const int PER = 16 * 1024;
    if (i >= 9 * PER) return;
    int k = i / PER;
    int r = i % PER;
    int og = r >> 10;
    int e = r & 1023;
    int c4 = e >> 5;
    int pair = (e >> 4) & 1;
    int ou = (e >> 1) & 7;
    int j = e & 1;
    int o = og * 8 + ou;
    int c = c4 * 4 + pair * 2 + j;
    g_wt7[i] = w[(o * NC + c) * 9 + k];
}

// ---------------------------------------------------------------------------
// Kernel 3: offset conv -> g_off (proven correct since R1)
// ---------------------------------------------------------------------------
__global__ void __launch_bounds__(256) k_off(const float* __restrict__ w_off,
                                             const float* __restrict__ b_off) {
    float* xin = dsm;                  // [3][64][128]
    float* sw  = dsm + 3 * NW * NC;    // [4][9][128]
    int h = blockIdx.x, b = blockIdx.y;
    int t = threadIdx.x;

    for (int r = 0; r < 3; r++) {
        int hr = h + r - 1;
        float4* dst = (float4*)(xin + r * NW * NC);
        if (hr >= 0 && hr < NH) {
            const float4* src = (const float4*)(g_xt + ((b * NH + hr) * NW) * NC);
            for (int i = t; i < (NW * NC) / 4; i += 256) dst[i] = src[i];
        } else {
            for (int i = t; i < (NW * NC) / 4; i += 256) dst[i] = make_float4(0.f, 0.f, 0.f, 0.f);
        }
    }
    for (int i = t; i < 4 * 9 * NC; i += 256) {
        int j = i / (9 * NC);
        int r2 = i % (9 * NC);
        int tap = r2 >> 7, c = r2 & 127;
        sw[i] = w_off[(j * NC + c) * 9 + tap];
    }
    __syncthreads();

    int wid = t >> 5, lane = t & 31;
    for (int it = 0; it < 8; it++) {
        int p = it * 8 + wid;
        float a0 = 0.f, a1 = 0.f, a2 = 0.f, a3 = 0.f;
#pragma unroll
        for (int tap = 0; tap < 9; tap++) {
            int dx = tap % 3 - 1;
            int dy = tap / 3;
            int xx = p + dx;
            if (xx < 0 || xx >= NW) continue;
            float4 xv = *(const float4*)(xin + (dy * NW + xx) * NC + lane * 4);
            float4 w0 = *(const float4*)(sw + (0 * 9 + tap) * NC + lane * 4);
            float4 w1 = *(const float4*)(sw + (1 * 9 + tap) * NC + lane * 4);
            float4 w2 = *(const float4*)(sw + (2 * 9 + tap) * NC + lane * 4);
            float4 w3 = *(const float4*)(sw + (3 * 9 + tap) * NC + lane * 4);
            a0 += xv.x * w0.x + xv.y * w0.y + xv.z * w0.z + xv.w * w0.w;
            a1 += xv.x * w1.x + xv.y * w1.y + xv.z * w1.z + xv.w * w1.w;
            a2 += xv.x * w2.x + xv.y * w2.y + xv.z * w2.z + xv.w * w2.w;
            a3 += xv.x * w3.x + xv.y * w3.y + xv.z * w3.z + xv.w * w3.w;
        }
#pragma unroll
        for (int off = 16; off; off >>= 1) {
            a0 += __shfl_xor_sync(0xffffffffu, a0, off);
            a1 += __shfl_xor_sync(0xffffffffu, a1, off);
            a2 += __shfl_xor_sync(0xffffffffu, a2, off);
            a3 += __shfl_xor_sync(0xffffffffu, a3, off);
        }
        if (lane == 0) {
            float sy = a0 + b_off[0];
            float sx = a1 + b_off[1];
            float s1 = fmaxf(a2 + b_off[2], 0.f) + 1.f;
            float s2 = fmaxf(a3 + b_off[3], 0.f) + 1.f;
            *(float4*)(g_off + ((b * NH + h) * NW + p) * 4) = make_float4(sy, sx, s1, s2);
        }
    }
}

// ---------------------------------------------------------------------------
// Split gather: samp_load issues corner math + 4 LDGs into registers;
// samp_store (>=4 GEMM chunks later) combines and writes the A tile.
// ---------------------------------------------------------------------------
struct GS {
    float4 v00, v01, v10, v11;
    float w00, w01, w10, w11;
    float* dst;
};

__device__ __forceinline__ void samp_load(int kk, int j, int half, GS& g,
                                          float4 pr, int wid, int lane, int h,
                                          const float* xb, float* nbuf) {
    int pxl = wid * 4 + j;             // local pixel 0..31
    int pw  = half * 32 + pxl;         // image w coordinate
    float sy = __shfl_sync(0xffffffffu, pr.x, j, 4);
    float sx = __shfl_sync(0xffffffffu, pr.y, j, 4);
    float s1 = __shfl_sync(0xffffffffu, pr.z, j, 4);
    float s2 = __shfl_sync(0xffffffffu, pr.w, j, 4);
    float sc = (kk & 1) ? s2 : s1;
    float py  = (float)h  + c_BY[kk] * sc + sy;
    float pxf = (float)pw + c_BX[kk] * sc + sx;
    float y0f = floorf(py), x0f = floorf(pxf);
    float wy = py - y0f, wx = pxf - x0f;
    int y0 = (int)y0f, x0 = (int)x0f;
    int y1 = y0 + 1, x1 = x0 + 1;
    float w00 = (1.f - wy) * (1.f - wx);
    float w01 = (1.f - wy) * wx;
    float w10 = wy * (1.f - wx);
    float w11 = wy * wx;
    bool vy0 = (y0 >= 0) && (y0 < NH), vy1 = (y1 >= 0) && (y1 < NH);
    bool vx0 = (x0 >= 0) && (x0 < NW), vx1 = (x1 >= 0) && (x1 < NW);
    g.w00 = (vy0 && vx0) ? w00 : 0.f;
    g.w01 = (vy0 && vx1) ? w01 : 0.f;
    g.w10 = (vy1 && vx0) ? w10 : 0.f;
    g.w11 = (vy1 && vx1) ? w11 : 0.f;
    int cy0 = min(max(y0, 0), NH - 1), cy1 = min(max(y1, 0), NH - 1);
    int cx0 = min(max(x0, 0), NW - 1), cx1 = min(max(x1, 0), NW - 1);
    g.v00 = *(const float4*)(xb + (cy0 * NW + cx0) * NC + lane * 4);
    g.v01 = *(const float4*)(xb + (cy0 * NW + cx1) * NC + lane * 4);
    g.v10 = *(const float4*)(xb + (cy1 * NW + cx0) * NC + lane * 4);
    g.v11 = *(const float4*)(xb + (cy1 * NW + cx1) * NC + lane * 4);
    int rot = pxl >> 3;
    int col = (lane + rot) & 31;
    g.dst = nbuf + pxl * 132 + col * 4;
}

__device__ __forceinline__ void samp_store(GS& g) {
    float4 s;
    s.x = g.w00 * g.v00.x + g.w01 * g.v01.x + g.w10 * g.v10.x + g.w11 * g.v11.x;
    s.y = g.w00 * g.v00.y + g.w01 * g.v01.y + g.w10 * g.v10.y + g.w11 * g.v11.y;
    s.z = g.w00 * g.v00.z + g.w01 * g.v01.z + g.w10 * g.v10.z + g.w11 * g.v11.z;
    s.w = g.w00 * g.v00.w + g.w01 * g.v01.w + g.w10 * g.v10.w + g.w11 * g.v11.w;
    *(float4*)g.dst = s;
}

// ---------------------------------------------------------------------------
// Kernel 4: deformable conv; W read directly via LDG (L1-resident, shared by
// both CTAs on the SM) — no smem W stage, no cp.async, one sync per tap.
// grid (2*NH, NB): CTA = 32 px (half row) x 128 outs, 256 thr, 2 CTA/SM.
// Thread map: pg = t&7 (4 px), og = (t>>3)&15 (8 outs), cs = t>>7 (ch half).
// Per 4-ch chunk: 4 A-LDS.128 (1 wf) + 4 W-LDG.128 (broadcast) + 64 FFMA2.
// ---------------------------------------------------------------------------
__global__ void __launch_bounds__(256, 2) k_main(const float* __restrict__ bias,
                                                 float* __restrict__ out) {
    float* Ab0 = dsm;              // [32][132]
    float* Ab1 = dsm + 4224;

    int h = blockIdx.x >> 1;
    int half = blockIdx.x & 1;
    int b = blockIdx.y;
    int t = threadIdx.x;
    int wid = t >> 5, lane = t & 31;
    int pg = t & 7;
    int og = (t >> 3) & 15;
    int cs = t >> 7;
    int rot = pg >> 1;

    int pw = half * 32 + wid * 4 + (lane & 3);
    float4 pr = *(const float4*)(g_off + ((b * NH + h) * NW + pw) * 4);
    const float* xb = g_xt + (size_t)b * (NH * NW * NC);

    unsigned long long acc[32];
#pragma unroll
    for (int i = 0; i < 32; i++) acc[i] = 0ull;

    GS G;
    // prologue: sample tap 0 (4 px/warp) into Ab0, immediate
#pragma unroll
    for (int j = 0; j < 4; j++) {
        samp_load(0, j, half, G, pr, wid, lane, h, xb, Ab0);
        samp_store(G);
    }

    for (int k = 0; k < 9; k++) {
        float* nbuf = (k & 1) ? Ab0 : Ab1;          // tap k+1 buffer
        const float* cbuf = (k & 1) ? Ab1 : Ab0;    // tap k buffer
        bool dos = (k < 8);
        if (dos) samp_load(k + 1, 0, half, G, pr, wid, lane, h, xb, nbuf);

        __syncthreads();           // prev GEMM done (nbuf free) + tap-k samples visible

        const float* arow = cbuf + pg * 4 * 132;
        const float* wrow = g_wt7 + ((size_t)k * 16 + og) * 1024;
#pragma unroll 1
        for (int j = 0; j < 16; j++) {
            if (dos && (j & 3) == 2) {
                samp_store(G);
                int i = j >> 2;
                if (i < 3) samp_load(k + 1, i + 1, half, G, pr, wid, lane, h, xb, nbuf);
            }
            int c4 = cs * 16 + j;
            int col = (c4 + rot) & 31;
            unsigned long long aA[4], aB[4];
#pragma unroll
            for (int i = 0; i < 4; i++) {
                ulonglong2 av = *(const ulonglong2*)(arow + i * 132 + col * 4);
                aA[i] = av.x;      // channels 4c4, 4c4+1
                aB[i] = av.y;      // channels 4c4+2, 4c4+3
            }
            const float* wp = wrow + c4 * 32;
            {   // ch pair (4c4, 4c4+1)
                ulonglong2 q0 = ((const ulonglong2*)wp)[0];
                ulonglong2 q1 = ((const ulonglong2*)wp)[1];
                ulonglong2 q2 = ((const ulonglong2*)wp)[2];
                ulonglong2 q3 = ((const ulonglong2*)wp)[3];
                unsigned long long wv[8] = {q0.x, q0.y, q1.x, q1.y,
                                            q2.x, q2.y, q3.x, q3.y};
#pragma unroll
                for (int i = 0; i < 4; i++)
#pragma unroll
                    for (int o = 0; o < 8; o++)
                        asm("fma.rn.f32x2 %0, %1, %2, %0;"
                            : "+l"(acc[i * 8 + o]) : "l"(wv[o]), "l"(aA[i]));
            }
            {   // ch pair (4c4+2, 4c4+3)
                const float* wq = wp + 16;
                ulonglong2 q0 = ((const ulonglong2*)wq)[0];
                ulonglong2 q1 = ((const ulonglong2*)wq)[1];
                ulonglong2 q2 = ((const ulonglong2*)wq)[2];
                ulonglong2 q3 = ((const ulonglong2*)wq)[3];
                unsigned long long wv[8] = {q0.x, q0.y, q1.x, q1.y,
                                            q2.x, q2.y, q3.x, q3.y};
#pragma unroll
                for (int i = 0; i < 4; i++)
#pragma unroll
                    for (int o = 0; o < 8; o++)
                        asm("fma.rn.f32x2 %0, %1, %2, %0;"
                            : "+l"(acc[i * 8 + o]) : "l"(wv[o]), "l"(aB[i]));
            }
        }
    }

    // ---- channel-split reduction + output ----
    float val[32];
#pragma unroll
    for (int e = 0; e < 32; e++) {
        float lo, hi;
        asm("mov.b64 {%0, %1}, %2;" : "=f"(lo), "=f"(hi) : "l"(acc[e]));
        val[e] = lo + hi;
    }
    __syncthreads();               // last GEMM reads done; A region reusable

    if (cs == 1) {                 // stage partials: stride 33 -> conflict-free
        int slot = t & 127;
#pragma unroll
        for (int e = 0; e < 32; e++) dsm[slot * 33 + e] = val[e];
    }
    __syncthreads();
    if (cs == 0) {
        int slot = t;
#pragma unroll
        for (int e = 0; e < 32; e++) val[e] += dsm[slot * 33 + e];
#pragma unroll
        for (int o = 0; o < 8; o++) {
            int oo = og * 8 + o;
            float bv = __ldg(bias + oo);
            float* op = out + (((size_t)b * NC + oo) * NH + h) * NW + half * 32 + pg * 4;
            *(float4*)op = make_float4(val[0 * 8 + o] + bv, val[1 * 8 + o] + bv,
                                       val[2 * 8 + o] + bv, val[3 * 8 + o] + bv);
        }
    }
}

// ---------------------------------------------------------------------------
extern "C" void kernel_launch(void* const* d_in, const int* in_sizes, int n_in,
                              void* d_out, int out_size) {
    const float* x     = (const float*)d_in[0];
    const float* w_off = (const float*)d_in[1];
    const float* b_off = (const float*)d_in[2];
    const float* w     = (const float*)d_in[3];
    const float* bias  = (const float*)d_in[4];
    float* out = (float*)d_out;

    k_transpose<<<dim3(NB * NH, NC / 32, NW / 32), dim3(32, 8)>>>(x);
    k_wt7<<<(9 * 16 * 1024 + 255) / 256, 256>>>(w);

    int off_smem = (3 * NW * NC + 4 * 9 * NC) * (int)sizeof(float);   // 116 KB
    cudaFuncSetAttribute(k_off, cudaFuncAttributeMaxDynamicSharedMemorySize, off_smem);
    k_off<<<dim3(NH, NB), 256, off_smem>>>(w_off, b_off);

    cudaFuncSetAttribute(k_main, cudaFuncAttributeMaxDynamicSharedMemorySize, KMAIN_SMEM);
    k_main<<<dim3(2 * NH, NB), 256, KMAIN_SMEM>>>(bias, out);
}

// round 17
// speedup vs baseline: 1.3837x; 1.3837x over previous
#include <cuda_runtime.h>

// Problem constants: B=8, CIN=COUT=128, H=W=64
#define NB   8
#define NC   128
#define NH   64
#define NW   64

// Scratch (device globals — no allocation allowed)
__device__ __align__(16) float g_xt[NB * NH * NW * NC];   // NHWC input, 16 MB
__device__ __align__(16) float g_off[NB * NH * NW * 4];   // shift_y, shift_x, scale1, scale2
__device__ __align__(16) float g_wt6[9 * 16 * 1028];      // [k][og16][1028] smem image

__constant__ float c_BY[9] = {-1,-1,-1, 0,0,0, 1,1,1};
__constant__ float c_BX[9] = {-1, 0, 1,-1,0,1,-1,0,1};

extern __shared__ float dsm[];

// k_main smem: A0 [32][132]=4224 | A1 4224 | W [16 og][1028]=16448 -> 24896 floats
#define WROW 1028
#define KMAIN_SMEM (24896 * 4)

// ---------------------------------------------------------------------------
// PTX helpers
// ---------------------------------------------------------------------------
__device__ __forceinline__ unsigned smaddr(const void* p) {
    return (unsigned)__cvta_generic_to_shared(p);
}
__device__ __forceinline__ void cpa16(unsigned d, const void* s) {
    asm volatile("cp.async.cg.shared.global [%0], [%1], 16;" :: "r"(d), "l"(s) : "memory");
}
__device__ __forceinline__ void cpa_commit() {
    asm volatile("cp.async.commit_group;" ::: "memory");
}
__device__ __forceinline__ void cpa_wait0() {
    asm volatile("cp.async.wait_group 0;" ::: "memory");
}

// ---------------------------------------------------------------------------
// Kernel 1: NCHW -> NHWC transpose
// ---------------------------------------------------------------------------
__global__ void k_transpose(const float* __restrict__ x) {
    __shared__ float tile[32][33];
    int bh = blockIdx.x;
    int b = bh >> 6, h = bh & 63;
    int c0 = blockIdx.y * 32;
    int w0 = blockIdx.z * 32;
    int tx = threadIdx.x, ty = threadIdx.y;
#pragma unroll
    for (int q = 0; q < 4; q++) {
        int c = c0 + ty + 8 * q;
        tile[ty + 8 * q][tx] = x[(((b * NC + c) * NH + h) * NW) + w0 + tx];
    }
    __syncthreads();
#pragma unroll
    for (int q = 0; q < 4; q++) {
        int w = w0 + ty + 8 * q;
        g_xt[((b * NH + h) * NW + w) * NC + c0 + tx] = tile[tx][ty + 8 * q];
    }
}

// ---------------------------------------------------------------------------
// Kernel 2: weight smem image. g_wt6[k][og][e], e<1024:
//   c4=e>>5, pair=(e>>4)&1, ou=(e>>1)&7, j=e&1
//   o = og*8 + ou,  c = c4*4 + pair*2 + j
// ---------------------------------------------------------------------------
__global__ void k_wt6(const float* __restrict__ w) {
    int i = blockIdx.x * 256 + threadIdx.x;
    const int PER = 16 * WROW;         // 16448 per k
    if (i >= 9 * PER) return;
    int k = i / PER;
    int r = i % PER;
    int og = r / WROW;
    int e = r % WROW;
    float val = 0.f;
    if (e < 1024) {
        int c4 = e >> 5;
        int pair = (e >> 4) & 1;
        int ou = (e >> 1) & 7;
        int j = e & 1;
        int o = og * 8 + ou;
        int c = c4 * 4 + pair * 2 + j;
        val = w[(o * NC + c) * 9 + k];
    }
    g_wt6[i] = val;
}

// ---------------------------------------------------------------------------
// Kernel 3: offset conv -> g_off (proven correct since R1)
// ---------------------------------------------------------------------------
__global__ void __launch_bounds__(256) k_off(const float* __restrict__ w_off,
                                             const float* __restrict__ b_off) {
    float* xin = dsm;                  // [3][64][128]
    float* sw  = dsm + 3 * NW * NC;    // [4][9][128]
    int h = blockIdx.x, b = blockIdx.y;
    int t = threadIdx.x;

    for (int r = 0; r < 3; r++) {
        int hr = h + r - 1;
        float4* dst = (float4*)(xin + r * NW * NC);
        if (hr >= 0 && hr < NH) {
            const float4* src = (const float4*)(g_xt + ((b * NH + hr) * NW) * NC);
            for (int i = t; i < (NW * NC) / 4; i += 256) dst[i] = src[i];
        } else {
            for (int i = t; i < (NW * NC) / 4; i += 256) dst[i] = make_float4(0.f, 0.f, 0.f, 0.f);
        }
    }
    for (int i = t; i < 4 * 9 * NC; i += 256) {
        int j = i / (9 * NC);
        int r2 = i % (9 * NC);
        int tap = r2 >> 7, c = r2 & 127;
        sw[i] = w_off[(j * NC + c) * 9 + tap];
    }
    __syncthreads();

    int wid = t >> 5, lane = t & 31;
    for (int it = 0; it < 8; it++) {
        int p = it * 8 + wid;
        float a0 = 0.f, a1 = 0.f, a2 = 0.f, a3 = 0.f;
#pragma unroll
        for (int tap = 0; tap < 9; tap++) {
            int dx = tap % 3 - 1;
            int dy = tap / 3;
            int xx = p + dx;
            if (xx < 0 || xx >= NW) continue;
            float4 xv = *(const float4*)(xin + (dy * NW + xx) * NC + lane * 4);
            float4 w0 = *(const float4*)(sw + (0 * 9 + tap) * NC + lane * 4);
            float4 w1 = *(const float4*)(sw + (1 * 9 + tap) * NC + lane * 4);
            float4 w2 = *(const float4*)(sw + (2 * 9 + tap) * NC + lane * 4);
            float4 w3 = *(const float4*)(sw + (3 * 9 + tap) * NC + lane * 4);
            a0 += xv.x * w0.x + xv.y * w0.y + xv.z * w0.z + xv.w * w0.w;
            a1 += xv.x * w1.x + xv.y * w1.y + xv.z * w1.z + xv.w * w1.w;
            a2 += xv.x * w2.x + xv.y * w2.y + xv.z * w2.z + xv.w * w2.w;
            a3 += xv.x * w3.x + xv.y * w3.y + xv.z * w3.z + xv.w * w3.w;
        }
#pragma unroll
        for (int off = 16; off; off >>= 1) {
            a0 += __shfl_xor_sync(0xffffffffu, a0, off);
            a1 += __shfl_xor_sync(0xffffffffu, a1, off);
            a2 += __shfl_xor_sync(0xffffffffu, a2, off);
            a3 += __shfl_xor_sync(0xffffffffu, a3, off);
        }
        if (lane == 0) {
            float sy = a0 + b_off[0];
            float sx = a1 + b_off[1];
            float s1 = fmaxf(a2 + b_off[2], 0.f) + 1.f;
            float s2 = fmaxf(a3 + b_off[3], 0.f) + 1.f;
            *(float4*)(g_off + ((b * NH + h) * NW + p) * 4) = make_float4(sy, sx, s1, s2);
        }
    }
}

// ---------------------------------------------------------------------------
// Split gather: samp_load issues corner math + 4 LDGs into registers;
// samp_store (>=4 GEMM chunks later) combines and writes the A tile.
// ---------------------------------------------------------------------------
struct GS {
    float4 v00, v01, v10, v11;
    float w00, w01, w10, w11;
    float* dst;
};

__device__ __forceinline__ void samp_load(int kk, int j, int half, GS& g,
                                          float4 pr, int wid, int lane, int h,
                                          const float* xb, float* nbuf) {
    int pxl = wid * 4 + j;             // local pixel 0..31
    int pw  = half * 32 + pxl;         // image w coordinate
    float sy = __shfl_sync(0xffffffffu, pr.x, j, 4);
    float sx = __shfl_sync(0xffffffffu, pr.y, j, 4);
    float s1 = __shfl_sync(0xffffffffu, pr.z, j, 4);
    float s2 = __shfl_sync(0xffffffffu, pr.w, j, 4);
    float sc = (kk & 1) ? s2 : s1;
    float py  = (float)h  + c_BY[kk] * sc + sy;
    float pxf = (float)pw + c_BX[kk] * sc + sx;
    float y0f = floorf(py), x0f = floorf(pxf);
    float wy = py - y0f, wx = pxf - x0f;
    int y0 = (int)y0f, x0 = (int)x0f;
    int y1 = y0 + 1, x1 = x0 + 1;
    float w00 = (1.f - wy) * (1.f - wx);
    float w01 = (1.f - wy) * wx;
    float w10 = wy * (1.f - wx);
    float w11 = wy * wx;
    bool vy0 = (y0 >= 0) && (y0 < NH), vy1 = (y1 >= 0) && (y1 < NH);
    bool vx0 = (x0 >= 0) && (x0 < NW), vx1 = (x1 >= 0) && (x1 < NW);
    g.w00 = (vy0 && vx0) ? w00 : 0.f;
    g.w01 = (vy0 && vx1) ? w01 : 0.f;
    g.w10 = (vy1 && vx0) ? w10 : 0.f;
    g.w11 = (vy1 && vx1) ? w11 : 0.f;
    int cy0 = min(max(y0, 0), NH - 1), cy1 = min(max(y1, 0), NH - 1);
    int cx0 = min(max(x0, 0), NW - 1), cx1 = min(max(x1, 0), NW - 1);
    g.v00 = *(const float4*)(xb + (cy0 * NW + cx0) * NC + lane * 4);
    g.v01 = *(const float4*)(xb + (cy0 * NW + cx1) * NC + lane * 4);
    g.v10 = *(const float4*)(xb + (cy1 * NW + cx0) * NC + lane * 4);
    g.v11 = *(const float4*)(xb + (cy1 * NW + cx1) * NC + lane * 4);
    int rot = pxl >> 3;
    int col = (lane + rot) & 31;
    g.dst = nbuf + pxl * 132 + col * 4;
}

__device__ __forceinline__ void samp_store(GS& g) {
    float4 s;
    s.x = g.w00 * g.v00.x + g.w01 * g.v01.x + g.w10 * g.v10.x + g.w11 * g.v11.x;
    s.y = g.w00 * g.v00.y + g.w01 * g.v01.y + g.w10 * g.v10.y + g.w11 * g.v11.y;
    s.z = g.w00 * g.v00.z + g.w01 * g.v01.z + g.w10 * g.v10.z + g.w11 * g.v11.z;
    s.w = g.w00 * g.v00.w + g.w01 * g.v01.w + g.w10 * g.v10.w + g.w11 * g.v11.w;
    *(float4*)g.dst = s;
}

// ---------------------------------------------------------------------------
// Kernel 4: deformable conv (R15 structure + hoisted cp.async addressing +
// branch-free 4x4 inner loop).
// grid (2*NH, NB): CTA = 32 px (half row) x 128 outs, 256 thr, 2 CTA/SM.
// Thread map: pg = t&7 (4 px), og = (t>>3)&15 (8 outs), cs = t>>7 (ch half).
// ---------------------------------------------------------------------------
__global__ void __launch_bounds__(256, 2) k_main(const float* __restrict__ bias,
                                                 float* __restrict__ out) {
    float* Ab0 = dsm;              // [32][132]
    float* Ab1 = dsm + 4224;
    float* wsm = dsm + 8448;       // [16 og][1028]

    int h = blockIdx.x >> 1;
    int half = blockIdx.x & 1;
    int b = blockIdx.y;
    int t = threadIdx.x;
    int wid = t >> 5, lane = t & 31;
    int pg = t & 7;
    int og = (t >> 3) & 15;
    int cs = t >> 7;
    int rot = pg >> 1;

    int pw = half * 32 + wid * 4 + (lane & 3);
    float4 pr = *(const float4*)(g_off + ((b * NH + h) * NW + pw) * 4);
    const float* xb = g_xt + (size_t)b * (NH * NW * NC);

    // hoisted W-copy addressing: thread t copies 16 (+1 if t<16) 16B segments
    unsigned wdst = smaddr(wsm) + (unsigned)t * 16;
    const float* wsrc0 = g_wt6 + (size_t)t * 4;

    unsigned long long acc[32];
#pragma unroll
    for (int i = 0; i < 32; i++) acc[i] = 0ull;

    GS G;
    // prologue: sample tap 0 (4 px/warp) into Ab0, immediate
#pragma unroll
    for (int j = 0; j < 4; j++) {
        samp_load(0, j, half, G, pr, wid, lane, h, xb, Ab0);
        samp_store(G);
    }

    for (int k = 0; k < 9; k++) {
        __syncthreads();           // prev GEMM done: W + next A buffer free

        // W tile: 16 fixed-offset cp.async (4096B apart) + 16-thread tail
        {
            const float* src = wsrc0 + (size_t)k * (16 * WROW);
#pragma unroll
            for (int q = 0; q < 16; q++)
                cpa16(wdst + q * 4096u, src + q * 1024);
            if (t < 16) cpa16(wdst + 16 * 4096u, src + 16 * 1024);
            cpa_commit();
        }

        float* nbuf = (k & 1) ? Ab0 : Ab1;          // tap k+1 buffer
        const float* cbuf = (k & 1) ? Ab1 : Ab0;    // tap k buffer
        bool dos = (k < 8);
        if (dos) samp_load(k + 1, 0, half, G, pr, wid, lane, h, xb, nbuf);

        cpa_wait0();
        __syncthreads();           // W + samples visible

        const float* arow = cbuf + pg * 4 * 132;
        const float* wrow = wsm + og * WROW;
#pragma unroll 1
        for (int jj = 0; jj < 4; jj++) {
            if (dos) {
                samp_store(G);     // px jj (loaded 4 chunks earlier)
                if (jj < 3) samp_load(k + 1, jj + 1, half, G, pr, wid, lane, h, xb, nbuf);
            }
#pragma unroll
            for (int q = 0; q < 4; q++) {
                int c4 = cs * 16 + jj * 4 + q;
                int col = (c4 + rot) & 31;
                unsigned long long aA[4], aB[4];
#pragma unroll
                for (int i = 0; i < 4; i++) {
                    ulonglong2 av = *(const ulonglong2*)(arow + i * 132 + col * 4);
                    aA[i] = av.x;      // channels 4c4, 4c4+1
                    aB[i] = av.y;      // channels 4c4+2, 4c4+3
                }
                const float* wp = wrow + c4 * 32;
                {   // ch pair (4c4, 4c4+1)
                    ulonglong2 q0 = ((const ulonglong2*)wp)[0];
                    ulonglong2 q1 = ((const ulonglong2*)wp)[1];
                    ulonglong2 q2 = ((const ulonglong2*)wp)[2];
                    ulonglong2 q3 = ((const ulonglong2*)wp)[3];
                    unsigned long long wv[8] = {q0.x, q0.y, q1.x, q1.y,
                                                q2.x, q2.y, q3.x, q3.y};
#pragma unroll
                    for (int i = 0; i < 4; i++)
#pragma unroll
                        for (int o = 0; o < 8; o++)
                            asm("fma.rn.f32x2 %0, %1, %2, %0;"
                                : "+l"(acc[i * 8 + o]) : "l"(wv[o]), "l"(aA[i]));
                }
                {   // ch pair (4c4+2, 4c4+3)
                    const float* wq = wp + 16;
                    ulonglong2 q0 = ((const ulonglong2*)wq)[0];
                    ulonglong2 q1 = ((const ulonglong2*)wq)[1];
                    ulonglong2 q2 = ((const ulonglong2*)wq)[2];
                    ulonglong2 q3 = ((const ulonglong2*)wq)[3];
                    unsigned long long wv[8] = {q0.x, q0.y, q1.x, q1.y,
                                                q2.x, q2.y, q3.x, q3.y};
#pragma unroll
                    for (int i = 0; i < 4; i++)
#pragma unroll
                        for (int o = 0; o < 8; o++)
                            asm("fma.rn.f32x2 %0, %1, %2, %0;"
                                : "+l"(acc[i * 8 + o]) : "l"(wv[o]), "l"(aB[i]));
                }
            }
        }
    }

    // ---- channel-split reduction + output ----
    float val[32];
#pragma unroll
    for (int e = 0; e < 32; e++) {
        float lo, hi;
        asm("mov.b64 {%0, %1}, %2;" : "=f"(lo), "=f"(hi) : "l"(acc[e]));
        val[e] = lo + hi;
    }
    __syncthreads();               // last GEMM reads done; A region reusable

    if (cs == 1) {                 // stage partials: stride 33 -> conflict-free
        int slot = t & 127;
#pragma unroll
        for (int e = 0; e < 32; e++) dsm[slot * 33 + e] = val[e];
    }
    __syncthreads();
    if (cs == 0) {
        int slot = t;
#pragma unroll
        for (int e = 0; e < 32; e++) val[e] += dsm[slot * 33 + e];
#pragma unroll
        for (int o = 0; o < 8; o++) {
            int oo = og * 8 + o;
            float bv = __ldg(bias + oo);
            float* op = out + (((size_t)b * NC + oo) * NH + h) * NW + half * 32 + pg * 4;
            *(float4*)op = make_float4(val[0 * 8 + o] + bv, val[1 * 8 + o] + bv,
                                       val[2 * 8 + o] + bv, val[3 * 8 + o] + bv);
        }
    }
}

// ---------------------------------------------------------------------------
extern "C" void kernel_launch(void* const* d_in, const int* in_sizes, int n_in,
                              void* d_out, int out_size) {
    const float* x     = (const float*)d_in[0];
    const float* w_off = (const float*)d_in[1];
    const float* b_off = (const float*)d_in[2];
    const float* w     = (const float*)d_in[3];
    const float* bias  = (const float*)d_in[4];
    float* out = (float*)d_out;

    k_transpose<<<dim3(NB * NH, NC / 32, NW / 32), dim3(32, 8)>>>(x);
    k_wt6<<<(9 * 16 * WROW + 255) / 256, 256>>>(w);

    int off_smem = (3 * NW * NC + 4 * 9 * NC) * (int)sizeof(float);   // 116 KB
    cudaFuncSetAttribute(k_off, cudaFuncAttributeMaxDynamicSharedMemorySize, off_smem);
    k_off<<<dim3(NH, NB), 256, off_smem>>>(w_off, b_off);

    cudaFuncSetAttribute(k_main, cudaFuncAttributeMaxDynamicSharedMemorySize, KMAIN_SMEM);
    k_main<<<dim3(2 * NH, NB), 256, KMAIN_SMEM>>>(bias, out);
}